// round 13
// baseline (speedup 1.0000x reference)
#include <cuda_runtime.h>
#include <cuda_fp16.h>

// Fused QLoRA-style block quantize + dequantize round trip.
// Input : float32, R rows of C=4096 contiguous elements (R = 4096 here).
// Per row: 64 blocks of 64 elems. Per block min/max -> scale; per-row 8-bit
// requant of scales; per element NF4 (16-level) nearest-table snap of the
// normalized value; immediate dequantize to the output.
//
// One CTA per row, 1024 threads, one float4 per thread. Single read + single
// write of the tensor => memory-bound (134 MB total traffic).

#define ROW_C 4096
#define THREADS_PER_CTA 1024

__global__ __launch_bounds__(THREADS_PER_CTA, 2)
void qlora_roundtrip_kernel(const float* __restrict__ in,
                            float* __restrict__ out) {
    __shared__ float sraw[16];     // raw f32 ndtri values
    __shared__ float stab[16];     // final table values (f32 of fp16)
    __shared__ float smid[16];     // 15 midpoints between adjacent table vals
    __shared__ float swmin[32];    // per-warp min of block scales
    __shared__ float swmax[32];    // per-warp max of block scales
    __shared__ float sred[2];      // row-level s_min / s_max

    const int t = threadIdx.x;
    const long long row = blockIdx.x;
    const float4* inp =
        reinterpret_cast<const float4*>(in + row * (long long)ROW_C);
    float4 v = inp[t];

    // ---- per-64-elem-block min/max: 16-lane group, 4 elems per thread ----
    float mn = fminf(fminf(v.x, v.y), fminf(v.z, v.w));
    float mx = fmaxf(fmaxf(v.x, v.y), fmaxf(v.z, v.w));
    #pragma unroll
    for (int off = 8; off >= 1; off >>= 1) {
        mn = fminf(mn, __shfl_xor_sync(0xffffffffu, mn, off));
        mx = fmaxf(mx, __shfl_xor_sync(0xffffffffu, mx, off));
    }
    const float sc = mx - mn;  // block scale (exact)

    // warp holds 2 blocks: combine their scales for the row reduction
    float wmn = fminf(sc, __shfl_xor_sync(0xffffffffu, sc, 16));
    float wmx = fmaxf(sc, __shfl_xor_sync(0xffffffffu, sc, 16));
    const int warp = t >> 5;
    const int lane = t & 31;
    if (lane == 0) { swmin[warp] = wmn; swmax[warp] = wmx; }

    // ---- NF table, phase 1: raw ndtri((i+0.5)/16) in f32 ----
    if (t < 16) {
        double p = ((double)t + 0.5) / 16.0;
        sraw[t] = (float)normcdfinv(p);
    }
    __syncthreads();

    // ---- NF table, phase 2: normalize, round to fp16, midpoints ----
    if (t < 16) {
        // table is monotone: max|q| is at one of the two ends
        float maxabs = fmaxf(fabsf(sraw[0]), fabsf(sraw[15]));
        float a = __half2float(__float2half_rn(sraw[t] / maxabs));
        stab[t] = a;
        if (t < 15) {
            float b = __half2float(__float2half_rn(sraw[t + 1] / maxabs));
            smid[t] = (a + b) * 0.5f;  // exact in f32 (sum of two fp16 vals)
        }
    }
    // row-level min/max over the 32 per-warp scale extremes (warp 1)
    if (warp == 1) {
        float rmn = swmin[lane], rmx = swmax[lane];
        #pragma unroll
        for (int off = 16; off >= 1; off >>= 1) {
            rmn = fminf(rmn, __shfl_xor_sync(0xffffffffu, rmn, off));
            rmx = fmaxf(rmx, __shfl_xor_sync(0xffffffffu, rmx, off));
        }
        if (lane == 0) { sred[0] = rmn; sred[1] = rmx; }
    }
    __syncthreads();

    // ---- 8-bit requantization of the block scale (per thread, once) ----
    const float s_min = sred[0];
    const float s_max = sred[1];
    // jnp.round == round-half-to-even == rintf
    const float q8 = rintf((sc - s_min) / (s_max - s_min + 1e-8f) * 255.0f);
    const float scale_r = s_min + q8 / 255.0f * (s_max - s_min);
    const float half_scale = 0.5f * scale_r;  // exact
    const float denom = sc + 1e-8f;

    // ---- per element: normalize, snap to nearest table value, dequant ----
    float xs[4] = {v.x, v.y, v.z, v.w};
    float os[4];
    #pragma unroll
    for (int e = 0; e < 4; e++) {
        // exactly the reference expression order (IEEE div)
        float xn = 2.0f * (xs[e] - mn) / denom - 1.0f;
        // nearest table entry, ties to lower index == argmin first-occurrence:
        // go right only on strict '>' vs the (exact) midpoint
        int idx = 0;
        if (xn > smid[7])       idx = 8;
        if (xn > smid[idx + 3]) idx += 4;
        if (xn > smid[idx + 1]) idx += 2;
        if (xn > smid[idx])     idx += 1;
        float w = stab[idx];
        // ((w+1)/2)*scale + min ; *0.5f and 0.5f*scale are exact halvings
        os[e] = (w + 1.0f) * half_scale + mn;
    }

    float4 o;
    o.x = os[0]; o.y = os[1]; o.z = os[2]; o.w = os[3];
    reinterpret_cast<float4*>(out + row * (long long)ROW_C)[t] = o;
}

extern "C" void kernel_launch(void* const* d_in, const int* in_sizes, int n_in,
                              void* d_out, int out_size) {
    const float* in = (const float*)d_in[0];
    float* out = (float*)d_out;
    const int rows = in_sizes[0] / ROW_C;  // 4*1024 = 4096 for this shape
    qlora_roundtrip_kernel<<<rows, THREADS_PER_CTA>>>(in, out);
}

// round 14
// speedup vs baseline: 2.5031x; 2.5031x over previous
#include <cuda_runtime.h>
#include <cuda_fp16.h>

// Fused QLoRA block quantize + dequantize round trip (NF4, BLOCK=64).
// One CTA (256 threads) per 4096-elem row; each thread owns 4 float4 chunks
// at t, t+256, t+512, t+768 (coalesced, MLP=4). Each 64-elem quant block maps
// to a 16-lane group; block min/max via 4-step shfl_xor. Per-row 8-bit
// requant of the 64 block scales via one cross-warp smem reduce (1 barrier).
// NF4 nearest-level snap done as a 4-level branchless binary search over
// midpoints: levels 1-3 with register selects, level 4 + table value via
// one warp shuffle each (no shared-memory lookups in the hot path).

#define ROW_C 4096
#define TPB   256

__global__ __launch_bounds__(TPB, 4)
void qlora_roundtrip_kernel(const float* __restrict__ in,
                            float* __restrict__ out) {
    __shared__ float s_tab[16];   // NF4 table (f32 of fp16 values)
    __shared__ float s_mid[16];   // 15 midpoints between adjacent levels
    __shared__ float swmin[8];    // per-warp min of block scales
    __shared__ float swmax[8];    // per-warp max of block scales

    const int t    = threadIdx.x;
    const int lane = t & 31;
    const int warp = t >> 5;
    const long long base = (long long)blockIdx.x * ROW_C;
    const float4* inp = reinterpret_cast<const float4*>(in + base);
    float4*       op  = reinterpret_cast<float4*>(out + base);

    // ---- issue all 4 loads up front (MLP=4) ----
    float4 v0 = inp[t];
    float4 v1 = inp[t + 256];
    float4 v2 = inp[t + 512];
    float4 v3 = inp[t + 768];

    // ---- NF4 table: warp 0 only, warp-level sync ----
    if (warp == 0) {
        float q = 0.0f;
        if (lane < 16) {
            float p = ((float)lane + 0.5f) * (1.0f / 16.0f);
            q = normcdfinvf(p);
            s_tab[lane] = q;
        }
        __syncwarp();
        if (lane < 16) {
            float maxabs = fmaxf(fabsf(s_tab[0]), fabsf(s_tab[15]));
            float a = __half2float(__float2half_rn(q / maxabs));
            s_tab[lane] = a;   // own slot only; safe after syncwarp
        }
        __syncwarp();
        if (lane < 15) {
            // midpoint of two fp16-representable values: exact in f32
            s_mid[lane] = 0.5f * (s_tab[lane] + s_tab[lane + 1]);
        }
    }

    // ---- per-block (64 elem = 16 lanes) min/max, 4 independent chains ----
    float mn0 = fminf(fminf(v0.x, v0.y), fminf(v0.z, v0.w));
    float mx0 = fmaxf(fmaxf(v0.x, v0.y), fmaxf(v0.z, v0.w));
    float mn1 = fminf(fminf(v1.x, v1.y), fminf(v1.z, v1.w));
    float mx1 = fmaxf(fmaxf(v1.x, v1.y), fmaxf(v1.z, v1.w));
    float mn2 = fminf(fminf(v2.x, v2.y), fminf(v2.z, v2.w));
    float mx2 = fmaxf(fmaxf(v2.x, v2.y), fmaxf(v2.z, v2.w));
    float mn3 = fminf(fminf(v3.x, v3.y), fminf(v3.z, v3.w));
    float mx3 = fmaxf(fmaxf(v3.x, v3.y), fmaxf(v3.z, v3.w));
    #pragma unroll
    for (int off = 8; off >= 1; off >>= 1) {
        mn0 = fminf(mn0, __shfl_xor_sync(0xffffffffu, mn0, off));
        mx0 = fmaxf(mx0, __shfl_xor_sync(0xffffffffu, mx0, off));
        mn1 = fminf(mn1, __shfl_xor_sync(0xffffffffu, mn1, off));
        mx1 = fmaxf(mx1, __shfl_xor_sync(0xffffffffu, mx1, off));
        mn2 = fminf(mn2, __shfl_xor_sync(0xffffffffu, mn2, off));
        mx2 = fmaxf(mx2, __shfl_xor_sync(0xffffffffu, mx2, off));
        mn3 = fminf(mn3, __shfl_xor_sync(0xffffffffu, mn3, off));
        mx3 = fmaxf(mx3, __shfl_xor_sync(0xffffffffu, mx3, off));
    }
    const float sc0 = mx0 - mn0;
    const float sc1 = mx1 - mn1;
    const float sc2 = mx2 - mn2;
    const float sc3 = mx3 - mn3;

    // ---- row-level min/max of the 64 block scales ----
    float tmn = fminf(fminf(sc0, sc1), fminf(sc2, sc3));
    float tmx = fmaxf(fmaxf(sc0, sc1), fmaxf(sc2, sc3));
    tmn = fminf(tmn, __shfl_xor_sync(0xffffffffu, tmn, 16));
    tmx = fmaxf(tmx, __shfl_xor_sync(0xffffffffu, tmx, 16));
    if (lane == 0) { swmin[warp] = tmn; swmax[warp] = tmx; }
    __syncthreads();   // single CTA-wide barrier

    float s_min_ = swmin[0], s_max_ = swmax[0];
    #pragma unroll
    for (int i = 1; i < 8; i++) {
        s_min_ = fminf(s_min_, swmin[i]);
        s_max_ = fmaxf(s_max_, swmax[i]);
    }

    // ---- per-lane table registers + uniform midpoints ----
    const float tabl = s_tab[lane & 15];          // lane l -> tab[l&15]
    const float emid = s_mid[2 * (lane & 7)];     // lane l -> mid[2(l&7)]
    const float m7  = s_mid[7];
    const float m3_ = s_mid[3],  m11 = s_mid[11];
    const float m1  = s_mid[1],  m5  = s_mid[5];
    const float m9  = s_mid[9],  m13 = s_mid[13];

    // ---- 8-bit requant of the 4 block scales ----
    const float rng     = s_max_ - s_min_;
    const float inv_rng = 255.0f / (rng + 1e-8f);
    const float q8_0 = rintf((sc0 - s_min_) * inv_rng);
    const float q8_1 = rintf((sc1 - s_min_) * inv_rng);
    const float q8_2 = rintf((sc2 - s_min_) * inv_rng);
    const float q8_3 = rintf((sc3 - s_min_) * inv_rng);
    const float hs0 = 0.5f * (s_min_ + q8_0 * (1.0f / 255.0f) * rng);
    const float hs1 = 0.5f * (s_min_ + q8_1 * (1.0f / 255.0f) * rng);
    const float hs2 = 0.5f * (s_min_ + q8_2 * (1.0f / 255.0f) * rng);
    const float hs3 = 0.5f * (s_min_ + q8_3 * (1.0f / 255.0f) * rng);
    const float r2_0 = 2.0f / (sc0 + 1e-8f);
    const float r2_1 = 2.0f / (sc1 + 1e-8f);
    const float r2_2 = 2.0f / (sc2 + 1e-8f);
    const float r2_3 = 2.0f / (sc3 + 1e-8f);
    const float bs0 = hs0 + mn0;
    const float bs1 = hs1 + mn1;
    const float bs2 = hs2 + mn2;
    const float bs3 = hs3 + mn3;

    // ---- per-element quantize + dequantize ----
    #define SNAP(x, MN, R2, HS, BS, O)                                       \
    {                                                                        \
        float xn = fmaf((x) - (MN), (R2), -1.0f);                            \
        bool p1 = xn > m7;                                                   \
        float mm2 = p1 ? m11 : m3_;                                          \
        bool p2 = xn > mm2;                                                  \
        float mlo = p2 ? m5 : m1;                                            \
        float mhi = p2 ? m13 : m9;                                           \
        float mm3 = p1 ? mhi : mlo;                                          \
        bool p3 = xn > mm3;                                                  \
        int s3 = (p1 ? 4 : 0) + (p2 ? 2 : 0) + (p3 ? 1 : 0);                 \
        float mm4 = __shfl_sync(0xffffffffu, emid, s3);                      \
        bool p4 = xn > mm4;                                                  \
        int idx = 2 * s3 + (p4 ? 1 : 0);                                     \
        float tv = __shfl_sync(0xffffffffu, tabl, idx);                      \
        (O) = fmaf(tv, (HS), (BS));                                          \
    }

    float4 o;
    SNAP(v0.x, mn0, r2_0, hs0, bs0, o.x);
    SNAP(v0.y, mn0, r2_0, hs0, bs0, o.y);
    SNAP(v0.z, mn0, r2_0, hs0, bs0, o.z);
    SNAP(v0.w, mn0, r2_0, hs0, bs0, o.w);
    op[t] = o;
    SNAP(v1.x, mn1, r2_1, hs1, bs1, o.x);
    SNAP(v1.y, mn1, r2_1, hs1, bs1, o.y);
    SNAP(v1.z, mn1, r2_1, hs1, bs1, o.z);
    SNAP(v1.w, mn1, r2_1, hs1, bs1, o.w);
    op[t + 256] = o;
    SNAP(v2.x, mn2, r2_2, hs2, bs2, o.x);
    SNAP(v2.y, mn2, r2_2, hs2, bs2, o.y);
    SNAP(v2.z, mn2, r2_2, hs2, bs2, o.z);
    SNAP(v2.w, mn2, r2_2, hs2, bs2, o.w);
    op[t + 512] = o;
    SNAP(v3.x, mn3, r2_3, hs3, bs3, o.x);
    SNAP(v3.y, mn3, r2_3, hs3, bs3, o.y);
    SNAP(v3.z, mn3, r2_3, hs3, bs3, o.z);
    SNAP(v3.w, mn3, r2_3, hs3, bs3, o.w);
    op[t + 768] = o;
    #undef SNAP
}

extern "C" void kernel_launch(void* const* d_in, const int* in_sizes, int n_in,
                              void* d_out, int out_size) {
    const float* in = (const float*)d_in[0];
    float* out = (float*)d_out;
    const int rows = in_sizes[0] / ROW_C;   // 4096 for this shape
    qlora_roundtrip_kernel<<<rows, TPB>>>(in, out);
}

// round 15
// speedup vs baseline: 2.7235x; 1.0881x over previous
#include <cuda_runtime.h>
#include <cuda_fp16.h>

// Fused QLoRA block quantize + dequantize round trip (NF4, BLOCK=64).
// One CTA (256 threads) per 4096-elem row. Each thread owns the 16 elements
// of ONE quarter of a 64-elem quant block: 4 threads per block, each thread
// loads 4 float4 strided 64B apart (coalesced at sector granularity).
// Block min/max = in-register 16-elem tree + 2 shfl_xor levels (4 lanes).
// Row-level 8-bit requant of the 64 block scales via 3 shfl levels + one
// smem barrier. NF4 nearest-level snap: 4-level binary search, levels 1-3
// via register selects, level 4 midpoint + table value via one shfl each.

#define ROW_C 4096
#define TPB   256

__global__ __launch_bounds__(TPB, 6)
void qlora_roundtrip_kernel(const float* __restrict__ in,
                            float* __restrict__ out) {
    __shared__ float s_tab[16];   // NF4 table (f32 of fp16 values)
    __shared__ float s_mid[16];   // 15 midpoints between adjacent levels
    __shared__ float swmin[8];    // per-warp min of block scales
    __shared__ float swmax[8];    // per-warp max of block scales

    const int t    = threadIdx.x;
    const int lane = t & 31;
    const int warp = t >> 5;
    const long long base = (long long)blockIdx.x * ROW_C;
    const float4* inp = reinterpret_cast<const float4*>(in + base);
    float4*       op  = reinterpret_cast<float4*>(out + base);

    // block id = t>>2 (64 blocks/row); this thread's 4 float4 chunks sit at
    // block*16 + (t&3) + {0,4,8,12}  (float4 units)
    const int fbase = ((t >> 2) << 4) + (t & 3);

    float4 v0 = inp[fbase];
    float4 v1 = inp[fbase + 4];
    float4 v2 = inp[fbase + 8];
    float4 v3 = inp[fbase + 12];

    // ---- NF4 table: warp 0 only, warp-level sync ----
    if (warp == 0) {
        float q = 0.0f;
        if (lane < 16) {
            float p = ((float)lane + 0.5f) * (1.0f / 16.0f);
            q = normcdfinvf(p);
            s_tab[lane] = q;
        }
        __syncwarp();
        if (lane < 16) {
            float maxabs = fmaxf(fabsf(s_tab[0]), fabsf(s_tab[15]));
            float a = __half2float(__float2half_rn(q / maxabs));
            s_tab[lane] = a;
        }
        __syncwarp();
        if (lane < 15) {
            // midpoint of two fp16-representable values: exact in f32
            s_mid[lane] = 0.5f * (s_tab[lane] + s_tab[lane + 1]);
        }
    }

    // ---- in-register min/max over this thread's 16 elements ----
    float mnA = fminf(fminf(v0.x, v0.y), fminf(v0.z, v0.w));
    float mxA = fmaxf(fmaxf(v0.x, v0.y), fmaxf(v0.z, v0.w));
    float mnB = fminf(fminf(v1.x, v1.y), fminf(v1.z, v1.w));
    float mxB = fmaxf(fmaxf(v1.x, v1.y), fmaxf(v1.z, v1.w));
    float mnC = fminf(fminf(v2.x, v2.y), fminf(v2.z, v2.w));
    float mxC = fmaxf(fmaxf(v2.x, v2.y), fmaxf(v2.z, v2.w));
    float mnD = fminf(fminf(v3.x, v3.y), fminf(v3.z, v3.w));
    float mxD = fmaxf(fmaxf(v3.x, v3.y), fmaxf(v3.z, v3.w));
    float mn = fminf(fminf(mnA, mnB), fminf(mnC, mnD));
    float mx = fmaxf(fmaxf(mxA, mxB), fmaxf(mxC, mxD));

    // ---- block (4-lane) min/max: 2 shuffle levels ----
    mn = fminf(mn, __shfl_xor_sync(0xffffffffu, mn, 1));
    mx = fmaxf(mx, __shfl_xor_sync(0xffffffffu, mx, 1));
    mn = fminf(mn, __shfl_xor_sync(0xffffffffu, mn, 2));
    mx = fmaxf(mx, __shfl_xor_sync(0xffffffffu, mx, 2));
    const float sc = mx - mn;   // block scale (exact)

    // ---- row-level min/max of block scales: warp reduce + smem ----
    float tmn = sc, tmx = sc;
    #pragma unroll
    for (int off = 4; off <= 16; off <<= 1) {
        tmn = fminf(tmn, __shfl_xor_sync(0xffffffffu, tmn, off));
        tmx = fmaxf(tmx, __shfl_xor_sync(0xffffffffu, tmx, off));
    }
    if (lane == 0) { swmin[warp] = tmn; swmax[warp] = tmx; }
    __syncthreads();   // single CTA-wide barrier

    float s_min_ = swmin[0], s_max_ = swmax[0];
    #pragma unroll
    for (int i = 1; i < 8; i++) {
        s_min_ = fminf(s_min_, swmin[i]);
        s_max_ = fmaxf(s_max_, swmax[i]);
    }

    // ---- per-lane table registers + uniform midpoints ----
    const float tabl = s_tab[lane & 15];          // lane l -> tab[l&15]
    const float emid = s_mid[2 * (lane & 7)];     // lane l -> mid[2(l&7)]
    const float m7  = s_mid[7];
    const float m3_ = s_mid[3],  m11 = s_mid[11];
    const float m1  = s_mid[1],  m5  = s_mid[5];
    const float m9  = s_mid[9],  m13 = s_mid[13];

    // ---- 8-bit requant of the block scale (once per thread) ----
    const float rng = s_max_ - s_min_;
    const float q8  = rintf((sc - s_min_) * (255.0f / (rng + 1e-8f)));
    const float hs  = 0.5f * (s_min_ + q8 * (1.0f / 255.0f) * rng);
    const float r2  = 2.0f / (sc + 1e-8f);
    const float bs  = hs + mn;

    // ---- per-element quantize + dequantize ----
    #define SNAP(x, O)                                                       \
    {                                                                        \
        float xn = fmaf((x) - mn, r2, -1.0f);                                \
        bool p1 = xn > m7;                                                   \
        float mm2 = p1 ? m11 : m3_;                                          \
        bool p2 = xn > mm2;                                                  \
        float mlo = p2 ? m5 : m1;                                            \
        float mhi = p2 ? m13 : m9;                                           \
        float mm3 = p1 ? mhi : mlo;                                          \
        bool p3 = xn > mm3;                                                  \
        int s3 = (p1 ? 4 : 0) + (p2 ? 2 : 0) + (p3 ? 1 : 0);                 \
        float mm4 = __shfl_sync(0xffffffffu, emid, s3);                      \
        bool p4 = xn > mm4;                                                  \
        int idx = 2 * s3 + (p4 ? 1 : 0);                                     \
        float tv = __shfl_sync(0xffffffffu, tabl, idx);                      \
        (O) = fmaf(tv, hs, bs);                                              \
    }

    float4 o;
    SNAP(v0.x, o.x); SNAP(v0.y, o.y); SNAP(v0.z, o.z); SNAP(v0.w, o.w);
    op[fbase] = o;
    SNAP(v1.x, o.x); SNAP(v1.y, o.y); SNAP(v1.z, o.z); SNAP(v1.w, o.w);
    op[fbase + 4] = o;
    SNAP(v2.x, o.x); SNAP(v2.y, o.y); SNAP(v2.z, o.z); SNAP(v2.w, o.w);
    op[fbase + 8] = o;
    SNAP(v3.x, o.x); SNAP(v3.y, o.y); SNAP(v3.z, o.z); SNAP(v3.w, o.w);
    op[fbase + 12] = o;
    #undef SNAP
}

extern "C" void kernel_launch(void* const* d_in, const int* in_sizes, int n_in,
                              void* d_out, int out_size) {
    const float* in = (const float*)d_in[0];
    float* out = (float*)d_out;
    const int rows = in_sizes[0] / ROW_C;   // 4096 for this shape
    qlora_roundtrip_kernel<<<rows, TPB>>>(in, out);
}

// round 16
// speedup vs baseline: 2.7605x; 1.0136x over previous
#include <cuda_runtime.h>
#include <cuda_fp16.h>

// Fused QLoRA block quantize + dequantize round trip (NF4, BLOCK=64).
// One CTA (256 threads) per 4096-elem row. Each thread owns the 16 elements
// of ONE quarter of a 64-elem quant block: 4 threads per block, each thread
// loads 4 float4 strided 64B apart (coalesced at sector granularity).
// Block min/max = in-register 16-elem tree + 2 shfl_xor levels (4 lanes).
// Row-level 8-bit requant of the 64 block scales via 3 shfl levels + one
// smem barrier. NF4 nearest-level snap: 4-level binary search, levels 1-3
// via register selects, level 4 midpoint + table value via one shfl each.

#define ROW_C 4096
#define TPB   256

__global__ __launch_bounds__(TPB, 6)
void qlora_roundtrip_kernel(const float* __restrict__ in,
                            float* __restrict__ out) {
    __shared__ float s_tab[16];   // NF4 table (f32 of fp16 values)
    __shared__ float s_mid[16];   // 15 midpoints between adjacent levels
    __shared__ float swmin[8];    // per-warp min of block scales
    __shared__ float swmax[8];    // per-warp max of block scales

    const int t    = threadIdx.x;
    const int lane = t & 31;
    const int warp = t >> 5;
    const long long base = (long long)blockIdx.x * ROW_C;
    const float4* inp = reinterpret_cast<const float4*>(in + base);
    float4*       op  = reinterpret_cast<float4*>(out + base);

    // block id = t>>2 (64 blocks/row); this thread's 4 float4 chunks sit at
    // block*16 + (t&3) + {0,4,8,12}  (float4 units)
    const int fbase = ((t >> 2) << 4) + (t & 3);

    float4 v0 = inp[fbase];
    float4 v1 = inp[fbase + 4];
    float4 v2 = inp[fbase + 8];
    float4 v3 = inp[fbase + 12];

    // ---- NF4 table: warp 0 only, warp-level sync ----
    if (warp == 0) {
        float q = 0.0f;
        if (lane < 16) {
            float p = ((float)lane + 0.5f) * (1.0f / 16.0f);
            q = normcdfinvf(p);
            s_tab[lane] = q;
        }
        __syncwarp();
        if (lane < 16) {
            float maxabs = fmaxf(fabsf(s_tab[0]), fabsf(s_tab[15]));
            float a = __half2float(__float2half_rn(q / maxabs));
            s_tab[lane] = a;
        }
        __syncwarp();
        if (lane < 15) {
            // midpoint of two fp16-representable values: exact in f32
            s_mid[lane] = 0.5f * (s_tab[lane] + s_tab[lane + 1]);
        }
    }

    // ---- in-register min/max over this thread's 16 elements ----
    float mnA = fminf(fminf(v0.x, v0.y), fminf(v0.z, v0.w));
    float mxA = fmaxf(fmaxf(v0.x, v0.y), fmaxf(v0.z, v0.w));
    float mnB = fminf(fminf(v1.x, v1.y), fminf(v1.z, v1.w));
    float mxB = fmaxf(fmaxf(v1.x, v1.y), fmaxf(v1.z, v1.w));
    float mnC = fminf(fminf(v2.x, v2.y), fminf(v2.z, v2.w));
    float mxC = fmaxf(fmaxf(v2.x, v2.y), fmaxf(v2.z, v2.w));
    float mnD = fminf(fminf(v3.x, v3.y), fminf(v3.z, v3.w));
    float mxD = fmaxf(fmaxf(v3.x, v3.y), fmaxf(v3.z, v3.w));
    float mn = fminf(fminf(mnA, mnB), fminf(mnC, mnD));
    float mx = fmaxf(fmaxf(mxA, mxB), fmaxf(mxC, mxD));

    // ---- block (4-lane) min/max: 2 shuffle levels ----
    mn = fminf(mn, __shfl_xor_sync(0xffffffffu, mn, 1));
    mx = fmaxf(mx, __shfl_xor_sync(0xffffffffu, mx, 1));
    mn = fminf(mn, __shfl_xor_sync(0xffffffffu, mn, 2));
    mx = fmaxf(mx, __shfl_xor_sync(0xffffffffu, mx, 2));
    const float sc = mx - mn;   // block scale (exact)

    // ---- row-level min/max of block scales: warp reduce + smem ----
    float tmn = sc, tmx = sc;
    #pragma unroll
    for (int off = 4; off <= 16; off <<= 1) {
        tmn = fminf(tmn, __shfl_xor_sync(0xffffffffu, tmn, off));
        tmx = fmaxf(tmx, __shfl_xor_sync(0xffffffffu, tmx, off));
    }
    if (lane == 0) { swmin[warp] = tmn; swmax[warp] = tmx; }
    __syncthreads();   // single CTA-wide barrier

    float s_min_ = swmin[0], s_max_ = swmax[0];
    #pragma unroll
    for (int i = 1; i < 8; i++) {
        s_min_ = fminf(s_min_, swmin[i]);
        s_max_ = fmaxf(s_max_, swmax[i]);
    }

    // ---- per-lane table registers + uniform midpoints ----
    const float tabl = s_tab[lane & 15];          // lane l -> tab[l&15]
    const float emid = s_mid[2 * (lane & 7)];     // lane l -> mid[2(l&7)]
    const float m7  = s_mid[7];
    const float m3_ = s_mid[3],  m11 = s_mid[11];
    const float m1  = s_mid[1],  m5  = s_mid[5];
    const float m9  = s_mid[9],  m13 = s_mid[13];

    // ---- 8-bit requant of the block scale (once per thread) ----
    const float rng = s_max_ - s_min_;
    const float q8  = rintf((sc - s_min_) * (255.0f / (rng + 1e-8f)));
    const float hs  = 0.5f * (s_min_ + q8 * (1.0f / 255.0f) * rng);
    const float r2  = 2.0f / (sc + 1e-8f);
    const float bs  = hs + mn;

    // ---- per-element quantize + dequantize ----
    #define SNAP(x, O)                                                       \
    {                                                                        \
        float xn = fmaf((x) - mn, r2, -1.0f);                                \
        bool p1 = xn > m7;                                                   \
        float mm2 = p1 ? m11 : m3_;                                          \
        bool p2 = xn > mm2;                                                  \
        float mlo = p2 ? m5 : m1;                                            \
        float mhi = p2 ? m13 : m9;                                           \
        float mm3 = p1 ? mhi : mlo;                                          \
        bool p3 = xn > mm3;                                                  \
        int s3 = (p1 ? 4 : 0) + (p2 ? 2 : 0) + (p3 ? 1 : 0);                 \
        float mm4 = __shfl_sync(0xffffffffu, emid, s3);                      \
        bool p4 = xn > mm4;                                                  \
        int idx = 2 * s3 + (p4 ? 1 : 0);                                     \
        float tv = __shfl_sync(0xffffffffu, tabl, idx);                      \
        (O) = fmaf(tv, hs, bs);                                              \
    }

    float4 o;
    SNAP(v0.x, o.x); SNAP(v0.y, o.y); SNAP(v0.z, o.z); SNAP(v0.w, o.w);
    op[fbase] = o;
    SNAP(v1.x, o.x); SNAP(v1.y, o.y); SNAP(v1.z, o.z); SNAP(v1.w, o.w);
    op[fbase + 4] = o;
    SNAP(v2.x, o.x); SNAP(v2.y, o.y); SNAP(v2.z, o.z); SNAP(v2.w, o.w);
    op[fbase + 8] = o;
    SNAP(v3.x, o.x); SNAP(v3.y, o.y); SNAP(v3.z, o.z); SNAP(v3.w, o.w);
    op[fbase + 12] = o;
    #undef SNAP
}

extern "C" void kernel_launch(void* const* d_in, const int* in_sizes, int n_in,
                              void* d_out, int out_size) {
    const float* in = (const float*)d_in[0];
    float* out = (float*)d_out;
    const int rows = in_sizes[0] / ROW_C;   // 4096 for this shape
    qlora_roundtrip_kernel<<<rows, TPB>>>(in, out);
}

// round 17
// speedup vs baseline: 2.8843x; 1.0449x over previous
#include <cuda_runtime.h>
#include <cuda_fp16.h>

// Fused QLoRA block quantize + dequantize round trip (NF4, BLOCK=64).
// One CTA (256 threads) per 4096-elem row. Each thread owns the 16 elements
// of ONE quarter of a 64-elem quant block: 4 threads per block, each thread
// loads 4 float4 strided 64B apart (coalesced at sector granularity).
// Block min/max = in-register 16-elem tree + 2 shfl_xor levels (4 lanes).
// Row-level 8-bit requant of the 64 block scales via 3 shfl levels + one
// smem barrier. NF4 nearest-level snap: 4-level binary search, levels 1-3
// via register selects, level 4 midpoint + table value via one shfl each.

#define ROW_C 4096
#define TPB   256

__global__ __launch_bounds__(TPB, 6)
void qlora_roundtrip_kernel(const float* __restrict__ in,
                            float* __restrict__ out) {
    __shared__ float s_tab[16];   // NF4 table (f32 of fp16 values)
    __shared__ float s_mid[16];   // 15 midpoints between adjacent levels
    __shared__ float swmin[8];    // per-warp min of block scales
    __shared__ float swmax[8];    // per-warp max of block scales

    const int t    = threadIdx.x;
    const int lane = t & 31;
    const int warp = t >> 5;
    const long long base = (long long)blockIdx.x * ROW_C;
    const float4* inp = reinterpret_cast<const float4*>(in + base);
    float4*       op  = reinterpret_cast<float4*>(out + base);

    // block id = t>>2 (64 blocks/row); this thread's 4 float4 chunks sit at
    // block*16 + (t&3) + {0,4,8,12}  (float4 units)
    const int fbase = ((t >> 2) << 4) + (t & 3);

    float4 v0 = inp[fbase];
    float4 v1 = inp[fbase + 4];
    float4 v2 = inp[fbase + 8];
    float4 v3 = inp[fbase + 12];

    // ---- NF4 table: warp 0 only, warp-level sync ----
    if (warp == 0) {
        float q = 0.0f;
        if (lane < 16) {
            float p = ((float)lane + 0.5f) * (1.0f / 16.0f);
            q = normcdfinvf(p);
            s_tab[lane] = q;
        }
        __syncwarp();
        if (lane < 16) {
            float maxabs = fmaxf(fabsf(s_tab[0]), fabsf(s_tab[15]));
            float a = __half2float(__float2half_rn(q / maxabs));
            s_tab[lane] = a;
        }
        __syncwarp();
        if (lane < 15) {
            // midpoint of two fp16-representable values: exact in f32
            s_mid[lane] = 0.5f * (s_tab[lane] + s_tab[lane + 1]);
        }
    }

    // ---- in-register min/max over this thread's 16 elements ----
    float mnA = fminf(fminf(v0.x, v0.y), fminf(v0.z, v0.w));
    float mxA = fmaxf(fmaxf(v0.x, v0.y), fmaxf(v0.z, v0.w));
    float mnB = fminf(fminf(v1.x, v1.y), fminf(v1.z, v1.w));
    float mxB = fmaxf(fmaxf(v1.x, v1.y), fmaxf(v1.z, v1.w));
    float mnC = fminf(fminf(v2.x, v2.y), fminf(v2.z, v2.w));
    float mxC = fmaxf(fmaxf(v2.x, v2.y), fmaxf(v2.z, v2.w));
    float mnD = fminf(fminf(v3.x, v3.y), fminf(v3.z, v3.w));
    float mxD = fmaxf(fmaxf(v3.x, v3.y), fmaxf(v3.z, v3.w));
    float mn = fminf(fminf(mnA, mnB), fminf(mnC, mnD));
    float mx = fmaxf(fmaxf(mxA, mxB), fmaxf(mxC, mxD));

    // ---- block (4-lane) min/max: 2 shuffle levels ----
    mn = fminf(mn, __shfl_xor_sync(0xffffffffu, mn, 1));
    mx = fmaxf(mx, __shfl_xor_sync(0xffffffffu, mx, 1));
    mn = fminf(mn, __shfl_xor_sync(0xffffffffu, mn, 2));
    mx = fmaxf(mx, __shfl_xor_sync(0xffffffffu, mx, 2));
    const float sc = mx - mn;   // block scale (exact)

    // ---- row-level min/max of block scales: warp reduce + smem ----
    float tmn = sc, tmx = sc;
    #pragma unroll
    for (int off = 4; off <= 16; off <<= 1) {
        tmn = fminf(tmn, __shfl_xor_sync(0xffffffffu, tmn, off));
        tmx = fmaxf(tmx, __shfl_xor_sync(0xffffffffu, tmx, off));
    }
    if (lane == 0) { swmin[warp] = tmn; swmax[warp] = tmx; }
    __syncthreads();   // single CTA-wide barrier

    float s_min_ = swmin[0], s_max_ = swmax[0];
    #pragma unroll
    for (int i = 1; i < 8; i++) {
        s_min_ = fminf(s_min_, swmin[i]);
        s_max_ = fmaxf(s_max_, swmax[i]);
    }

    // ---- per-lane table registers + uniform midpoints ----
    const float tabl = s_tab[lane & 15];          // lane l -> tab[l&15]
    const float emid = s_mid[2 * (lane & 7)];     // lane l -> mid[2(l&7)]
    const float m7  = s_mid[7];
    const float m3_ = s_mid[3],  m11 = s_mid[11];
    const float m1  = s_mid[1],  m5  = s_mid[5];
    const float m9  = s_mid[9],  m13 = s_mid[13];

    // ---- 8-bit requant of the block scale (once per thread) ----
    const float rng = s_max_ - s_min_;
    const float q8  = rintf((sc - s_min_) * (255.0f / (rng + 1e-8f)));
    const float hs  = 0.5f * (s_min_ + q8 * (1.0f / 255.0f) * rng);
    const float r2  = 2.0f / (sc + 1e-8f);
    const float bs  = hs + mn;

    // ---- per-element quantize + dequantize ----
    #define SNAP(x, O)                                                       \
    {                                                                        \
        float xn = fmaf((x) - mn, r2, -1.0f);                                \
        bool p1 = xn > m7;                                                   \
        float mm2 = p1 ? m11 : m3_;                                          \
        bool p2 = xn > mm2;                                                  \
        float mlo = p2 ? m5 : m1;                                            \
        float mhi = p2 ? m13 : m9;                                           \
        float mm3 = p1 ? mhi : mlo;                                          \
        bool p3 = xn > mm3;                                                  \
        int s3 = (p1 ? 4 : 0) + (p2 ? 2 : 0) + (p3 ? 1 : 0);                 \
        float mm4 = __shfl_sync(0xffffffffu, emid, s3);                      \
        bool p4 = xn > mm4;                                                  \
        int idx = 2 * s3 + (p4 ? 1 : 0);                                     \
        float tv = __shfl_sync(0xffffffffu, tabl, idx);                      \
        (O) = fmaf(tv, hs, bs);                                              \
    }

    float4 o;
    SNAP(v0.x, o.x); SNAP(v0.y, o.y); SNAP(v0.z, o.z); SNAP(v0.w, o.w);
    op[fbase] = o;
    SNAP(v1.x, o.x); SNAP(v1.y, o.y); SNAP(v1.z, o.z); SNAP(v1.w, o.w);
    op[fbase + 4] = o;
    SNAP(v2.x, o.x); SNAP(v2.y, o.y); SNAP(v2.z, o.z); SNAP(v2.w, o.w);
    op[fbase + 8] = o;
    SNAP(v3.x, o.x); SNAP(v3.y, o.y); SNAP(v3.z, o.z); SNAP(v3.w, o.w);
    op[fbase + 12] = o;
    #undef SNAP
}

extern "C" void kernel_launch(void* const* d_in, const int* in_sizes, int n_in,
                              void* d_out, int out_size) {
    const float* in = (const float*)d_in[0];
    float* out = (float*)d_out;
    const int rows = in_sizes[0] / ROW_C;   // 4096 for this shape
    qlora_roundtrip_kernel<<<rows, TPB>>>(in, out);
}